// round 1
// baseline (speedup 1.0000x reference)
#include <cuda_runtime.h>

// Problem constants
#define Bb 4
#define Nn 2048
#define Dd 512
#define Hh 8
#define Cc 64
#define HC 512   // H*C

// Scratch (device globals; no runtime allocation allowed)
__device__ float g_x[Bb * Nn * HC];        // projected features [B,N,H,C]
__device__ float g_asrc[Bb * Nn * Hh];
__device__ float g_adst[Bb * Nn * Hh];
__device__ float g_EA [Bb * Nn * Hh];      // exp(a_src)
__device__ float g_EA2[Bb * Nn * Hh];      // exp(0.2*a_src)
__device__ float g_EB [Bb * Nn * Hh];      // exp(a_dst)
__device__ float g_EB2[Bb * Nn * Hh];      // exp(0.2*a_dst)

// ---------------------------------------------------------------------------
// Kernel 1: projection GEMM  x[8192,512] = feat[8192,512] @ W[512,512]
// Tile: 128(M) x 64(N), BK=16, 128 threads, 8x8 microtile.
// ---------------------------------------------------------------------------
__global__ __launch_bounds__(128) void proj_kernel(const float* __restrict__ A,
                                                   const float* __restrict__ Wm) {
    __shared__ float As[16][132];   // transposed A tile (k-major)
    __shared__ float Bs[16][64];

    const int t  = threadIdx.x;
    const int tj = t & 15;          // 0..15  -> M groups
    const int tc = t >> 4;          // 0..7   -> N groups
    const int m0 = blockIdx.x * 128;
    const int n0 = blockIdx.y * 64;

    float acc[64];
#pragma unroll
    for (int i = 0; i < 64; i++) acc[i] = 0.f;

    for (int k0 = 0; k0 < Dd; k0 += 16) {
        // A tile: each thread loads one 16-float row, stores transposed
#pragma unroll
        for (int q = 0; q < 4; q++) {
            float4 v = *(const float4*)&A[(m0 + t) * Dd + k0 + q * 4];
            As[q * 4 + 0][t] = v.x;
            As[q * 4 + 1][t] = v.y;
            As[q * 4 + 2][t] = v.z;
            As[q * 4 + 3][t] = v.w;
        }
        // B tile: 16x64 = 1024 floats, 8 per thread
#pragma unroll
        for (int q = 0; q < 2; q++) {
            int idx = t + 128 * q;
            int r = idx >> 4, c4 = idx & 15;
            *(float4*)&Bs[r][c4 * 4] =
                *(const float4*)&Wm[(k0 + r) * HC + n0 + c4 * 4];
        }
        __syncthreads();

#pragma unroll
        for (int k = 0; k < 16; k++) {
            float a0[8], b0[8];
            *(float4*)&a0[0] = *(const float4*)&As[k][tj * 4];
            *(float4*)&a0[4] = *(const float4*)&As[k][64 + tj * 4];
            *(float4*)&b0[0] = *(const float4*)&Bs[k][tc * 4];
            *(float4*)&b0[4] = *(const float4*)&Bs[k][32 + tc * 4];
#pragma unroll
            for (int u = 0; u < 8; u++)
#pragma unroll
                for (int v = 0; v < 8; v++)
                    acc[u * 8 + v] += a0[u] * b0[v];
        }
        __syncthreads();
    }

#pragma unroll
    for (int g = 0; g < 2; g++)
#pragma unroll
        for (int u = 0; u < 4; u++) {
            int m = m0 + g * 64 + tj * 4 + u;
#pragma unroll
            for (int gc = 0; gc < 2; gc++) {
                float4 v;
                v.x = acc[(g * 4 + u) * 8 + gc * 4 + 0];
                v.y = acc[(g * 4 + u) * 8 + gc * 4 + 1];
                v.z = acc[(g * 4 + u) * 8 + gc * 4 + 2];
                v.w = acc[(g * 4 + u) * 8 + gc * 4 + 3];
                *(float4*)&g_x[m * HC + n0 + gc * 32 + tc * 4] = v;
            }
        }
}

// ---------------------------------------------------------------------------
// Kernel 2: per-(b,n,h) attention scalars + exp tables.
// exp(leaky(a_i+b_j)) = (a_i+b_j>0) ? e^{a_i} e^{b_j} : e^{.2 a_i} e^{.2 b_j}
// ---------------------------------------------------------------------------
__global__ void attn_prep(const float* __restrict__ att_src,
                          const float* __restrict__ att_dst) {
    __shared__ float s_as[HC], s_ad[HC];
    for (int i = threadIdx.x; i < HC; i += blockDim.x) {
        s_as[i] = att_src[i];
        s_ad[i] = att_dst[i];
    }
    __syncthreads();

    int tid = blockIdx.x * blockDim.x + threadIdx.x;   // 0..B*N*H-1
    int h  = tid & (Hh - 1);
    int bn = tid >> 3;
    const float* xr = g_x + bn * HC + h * Cc;
    float a = 0.f, d = 0.f;
#pragma unroll
    for (int c = 0; c < Cc; c += 4) {
        float4 xv = *(const float4*)&xr[c];
        float4 sv = *(const float4*)&s_as[h * Cc + c];
        float4 dv = *(const float4*)&s_ad[h * Cc + c];
        a += xv.x * sv.x + xv.y * sv.y + xv.z * sv.z + xv.w * sv.w;
        d += xv.x * dv.x + xv.y * dv.y + xv.z * dv.z + xv.w * dv.w;
    }
    g_asrc[tid] = a;
    g_adst[tid] = d;
    g_EA [tid] = expf(a);
    g_EA2[tid] = expf(0.2f * a);
    g_EB [tid] = expf(d);
    g_EB2[tid] = expf(0.2f * d);
}

// ---------------------------------------------------------------------------
// Kernel 3: fused masked-softmax aggregation.
// CTA = (h, j_tile of 128, b). out[j,c] = (sum_i w[i,j] x[i,h,c]) / sum_i w
// P tile fabricated in SMEM (no exp: table products), then 128x64 GEMM tile.
// 128 threads: build phase each thread owns one j column; GEMM 8x8 microtile.
// ---------------------------------------------------------------------------
__global__ __launch_bounds__(128) void gat_agg(const int* __restrict__ adj,
                                               const float* __restrict__ bias,
                                               float* __restrict__ out) {
    __shared__ float Ps[32][132];
    __shared__ float Xs[32][64];
    __shared__ float sA[32], sEA[32], sEA2[32];
    __shared__ float sDen[128];

    const int h  = blockIdx.x;          // fastest -> 8 heads share adj tile in L2
    const int j0 = blockIdx.y * 128;
    const int b  = blockIdx.z;

    const int t  = threadIdx.x;
    const int tj = t & 15;
    const int tc = t >> 4;
    const int jg = j0 + t;              // this thread's j column (build phase)

    const int jrow = (b * Nn + jg) * Hh + h;
    const float bj   = g_adst[jrow];
    const float EBj  = g_EB [jrow];
    const float EB2j = g_EB2[jrow];

    const int* adj_b = adj + b * Nn * Nn;

    float den = 0.f;
    float acc[64];
#pragma unroll
    for (int i = 0; i < 64; i++) acc[i] = 0.f;

    for (int i0 = 0; i0 < Nn; i0 += 32) {
        __syncthreads();   // previous GEMM done before overwriting Xs/Ps

        // stage per-i scalars
        if (t < 32)       sA  [t]      = g_asrc[(b * Nn + i0 + t)        * Hh + h];
        else if (t < 64)  sEA [t - 32] = g_EA  [(b * Nn + i0 + (t - 32)) * Hh + h];
        else if (t < 96)  sEA2[t - 64] = g_EA2 [(b * Nn + i0 + (t - 64)) * Hh + h];

        // load x tile [32 i][64 c]
#pragma unroll
        for (int q = 0; q < 4; q++) {
            int idx = t + 128 * q;
            int r = idx >> 4, c4 = idx & 15;
            *(float4*)&Xs[r][c4 * 4] =
                *(const float4*)&g_x[((b * Nn + i0 + r) * Hh + h) * Cc + c4 * 4];
        }
        __syncthreads();

        // build P tile: thread t owns column j=jg, rows i0..i0+31
#pragma unroll
        for (int ii = 0; ii < 32; ii += 8) {
            int av[8];
#pragma unroll
            for (int k = 0; k < 8; k++)
                av[k] = adj_b[(i0 + ii + k) * Nn + jg];
#pragma unroll
            for (int k = 0; k < 8; k++) {
                int i  = ii + k;
                int ig = i0 + i;
                float m = (av[k] != 0 || ig == jg) ? 1.f : 0.f;
                float s = sA[i] + bj;
                float w = (s > 0.f ? sEA[i] * EBj : sEA2[i] * EB2j) * m;
                Ps[i][t] = w;
                den += w;
            }
        }
        __syncthreads();

        // GEMM: acc[j,c] += P[i,j] * X[i,c]
#pragma unroll
        for (int i = 0; i < 32; i++) {
            float p[8], x[8];
            *(float4*)&p[0] = *(const float4*)&Ps[i][tj * 4];
            *(float4*)&p[4] = *(const float4*)&Ps[i][64 + tj * 4];
            *(float4*)&x[0] = *(const float4*)&Xs[i][tc * 4];
            *(float4*)&x[4] = *(const float4*)&Xs[i][32 + tc * 4];
#pragma unroll
            for (int u = 0; u < 8; u++)
#pragma unroll
                for (int v = 0; v < 8; v++)
                    acc[u * 8 + v] += p[u] * x[v];
        }
    }

    __syncthreads();
    sDen[t] = den;
    __syncthreads();

    // epilogue: normalize, +bias, ELU, store
#pragma unroll
    for (int g = 0; g < 2; g++)
#pragma unroll
        for (int u = 0; u < 4; u++) {
            int j = g * 64 + tj * 4 + u;
            float rd = 1.f / sDen[j];
            int row = (b * Nn + j0 + j) * HC + h * Cc;
#pragma unroll
            for (int gc = 0; gc < 2; gc++) {
                float4 v;
                float r0 = acc[(g * 4 + u) * 8 + gc * 4 + 0] * rd + bias[h * Cc + gc * 32 + tc * 4 + 0];
                float r1 = acc[(g * 4 + u) * 8 + gc * 4 + 1] * rd + bias[h * Cc + gc * 32 + tc * 4 + 1];
                float r2 = acc[(g * 4 + u) * 8 + gc * 4 + 2] * rd + bias[h * Cc + gc * 32 + tc * 4 + 2];
                float r3 = acc[(g * 4 + u) * 8 + gc * 4 + 3] * rd + bias[h * Cc + gc * 32 + tc * 4 + 3];
                v.x = r0 > 0.f ? r0 : expf(r0) - 1.f;
                v.y = r1 > 0.f ? r1 : expf(r1) - 1.f;
                v.z = r2 > 0.f ? r2 : expf(r2) - 1.f;
                v.w = r3 > 0.f ? r3 : expf(r3) - 1.f;
                *(float4*)&out[row + gc * 32 + tc * 4] = v;
            }
        }
}

// ---------------------------------------------------------------------------
extern "C" void kernel_launch(void* const* d_in, const int* in_sizes, int n_in,
                              void* d_out, int out_size) {
    const float* feat    = (const float*)d_in[0];   // [4,2048,512]
    const int*   adj     = (const int*)  d_in[1];   // [4,2048,2048]
    const float* W       = (const float*)d_in[2];   // [512,512]
    const float* att_src = (const float*)d_in[3];   // [8,64]
    const float* att_dst = (const float*)d_in[4];   // [8,64]
    const float* bias    = (const float*)d_in[5];   // [512]
    float* out = (float*)d_out;                     // [4,2048,512]

    proj_kernel<<<dim3(64, 8), 128>>>(feat, W);
    attn_prep<<<(Bb * Nn * Hh) / 256, 256>>>(att_src, att_dst);
    gat_agg<<<dim3(Hh, Nn / 128, Bb), 128>>>(adj, bias, out);
}

// round 4
// speedup vs baseline: 2.0345x; 2.0345x over previous
#include <cuda_runtime.h>
#include <cuda_bf16.h>
#include <cstdint>

#define Bb 4
#define Nn 2048
#define Dd 512
#define Hh 8
#define Cc 64
#define HC 512

// ---------------- device scratch ----------------
__device__ float g_x[(size_t)Bb * Nn * HC];                 // [B,N,H,C] fp32
__device__ float g_EAH [Bb * Hh * Nn];                      // exp(a_src)   [B,H,N]
__device__ float g_EA2H[Bb * Hh * Nn];                      // exp(.2 a_src)
__device__ float g_EBH [Bb * Hh * Nn];                      // exp(a_dst)
__device__ float g_EB2H[Bb * Hh * Nn];
__device__ unsigned g_bitT[(size_t)Bb * Nn * (Nn / 32)];    // mask^T incl self-loops
__device__ __align__(16) __nv_bfloat16 g_xThi[(size_t)Bb * Hh * Cc * Nn]; // [B,H,C,N]
__device__ __align__(16) __nv_bfloat16 g_xTlo[(size_t)Bb * Hh * Cc * Nn];
__device__ __align__(16) __nv_bfloat16 g_fhi[(size_t)Bb * Nn * Dd];       // feat hi
__device__ __align__(16) __nv_bfloat16 g_flo[(size_t)Bb * Nn * Dd];
__device__ __align__(16) __nv_bfloat16 g_wthi[HC * Dd];                   // W^T [n][k]
__device__ __align__(16) __nv_bfloat16 g_wtlo[HC * Dd];

// ---------------- helpers ----------------
__device__ __forceinline__ uint32_t smem_u32(const void* p) {
    uint32_t a;
    asm("{ .reg .u64 t; cvta.to.shared.u64 t, %1; cvt.u32.u64 %0, t; }" : "=r"(a) : "l"(p));
    return a;
}
// SW128-swizzled byte offset, 128B-pitch tile: (row, 16B-granule)
__device__ __forceinline__ unsigned swz(unsigned r, unsigned kb) {
    return r * 128u + ((kb ^ (r & 7u)) << 4);
}
__device__ __forceinline__ void ldsm4(uint32_t addr, unsigned& r0, unsigned& r1,
                                      unsigned& r2, unsigned& r3) {
    asm volatile("ldmatrix.sync.aligned.m8n8.x4.shared.b16 {%0,%1,%2,%3}, [%4];"
                 : "=r"(r0), "=r"(r1), "=r"(r2), "=r"(r3) : "r"(addr));
}
__device__ __forceinline__ void mma4(float* c, const unsigned a[4], unsigned b0, unsigned b1) {
    asm volatile("mma.sync.aligned.m16n8k16.row.col.f32.bf16.bf16.f32 "
                 "{%0,%1,%2,%3}, {%4,%5,%6,%7}, {%8,%9}, {%0,%1,%2,%3};"
                 : "+f"(c[0]), "+f"(c[1]), "+f"(c[2]), "+f"(c[3])
                 : "r"(a[0]), "r"(a[1]), "r"(a[2]), "r"(a[3]), "r"(b0), "r"(b1));
}

// One warp: acc[nt][4] += A(16x64) x B^T(64x64), 3-term bf16 hi/lo.
// A rows wrow..wrow+15 of the A tile; B rows = n (0..63), k contiguous.
__device__ __forceinline__ void warp_mma_16x64(float (&acc)[8][4],
                                               uint32_t aHi, uint32_t aLo,
                                               uint32_t bHi, uint32_t bLo,
                                               int lane, int wrow) {
#pragma unroll
    for (int ks = 0; ks < 4; ks++) {
        unsigned ah[4], al[4];
        unsigned offA = swz(wrow + (lane & 15), ks * 2 + (lane >> 4));
        ldsm4(aHi + offA, ah[0], ah[1], ah[2], ah[3]);
        ldsm4(aLo + offA, al[0], al[1], al[2], al[3]);
        unsigned brow = (lane & 7) + ((lane >> 4) << 3);
        unsigned bkb = ks * 2 + ((lane >> 3) & 1);
#pragma unroll
        for (int np = 0; np < 4; np++) {
            unsigned off = swz(brow + np * 16, bkb);
            unsigned h0, h1, h2, h3, l0, l1, l2, l3;
            ldsm4(bHi + off, h0, h1, h2, h3);
            ldsm4(bLo + off, l0, l1, l2, l3);
            mma4(acc[2 * np],     ah, h0, h1);
            mma4(acc[2 * np],     ah, l0, l1);
            mma4(acc[2 * np],     al, h0, h1);
            mma4(acc[2 * np + 1], ah, h2, h3);
            mma4(acc[2 * np + 1], ah, l2, l3);
            mma4(acc[2 * np + 1], al, h2, h3);
        }
    }
}

// ---------------------------------------------------------------------------
// decompose feat -> hi/lo bf16
// ---------------------------------------------------------------------------
__global__ __launch_bounds__(256) void decomp_feat(const float* __restrict__ f) {
    size_t idx = (size_t)blockIdx.x * 256 + threadIdx.x;   // float4 index
    float4 v = ((const float4*)f)[idx];
    __nv_bfloat162 h01 = __floats2bfloat162_rn(v.x, v.y);
    __nv_bfloat162 h23 = __floats2bfloat162_rn(v.z, v.w);
    unsigned hb0 = *(unsigned*)&h01, hb1 = *(unsigned*)&h23;
    float r0 = v.x - __uint_as_float(hb0 << 16);
    float r1 = v.y - __uint_as_float(hb0 & 0xFFFF0000u);
    float r2 = v.z - __uint_as_float(hb1 << 16);
    float r3 = v.w - __uint_as_float(hb1 & 0xFFFF0000u);
    __nv_bfloat162 l01 = __floats2bfloat162_rn(r0, r1);
    __nv_bfloat162 l23 = __floats2bfloat162_rn(r2, r3);
    ((uint2*)g_fhi)[idx] = make_uint2(hb0, hb1);
    ((uint2*)g_flo)[idx] = make_uint2(*(unsigned*)&l01, *(unsigned*)&l23);
}

// ---------------------------------------------------------------------------
// W [k][n] -> W^T hi/lo [n][k]
// ---------------------------------------------------------------------------
__global__ __launch_bounds__(256) void decomp_wt(const float* __restrict__ Wm) {
    __shared__ float s[32][33];
    const int k0 = blockIdx.x * 32, n0 = blockIdx.y * 32;
    const int t = threadIdx.x, r = t >> 5, c = t & 31;
#pragma unroll
    for (int q = 0; q < 4; q++)
        s[r + 8 * q][c] = Wm[(size_t)(k0 + r + 8 * q) * HC + n0 + c];
    __syncthreads();
#pragma unroll
    for (int q = 0; q < 4; q++) {
        int n = r + 8 * q;
        float v = s[c][n];
        __nv_bfloat16 hi = __float2bfloat16(v);
        __nv_bfloat16 lo = __float2bfloat16(v - __bfloat162float(hi));
        g_wthi[(size_t)(n0 + n) * Dd + k0 + c] = hi;
        g_wtlo[(size_t)(n0 + n) * Dd + k0 + c] = lo;
    }
}

// ---------------------------------------------------------------------------
// adjacency -> transposed bitmask (with self-loops)
// ---------------------------------------------------------------------------
__global__ __launch_bounds__(256) void pack_adj(const int* __restrict__ adj) {
    __shared__ int s[32][256];
    const int b = blockIdx.z, i0 = blockIdx.x * 32, j0 = blockIdx.y * 256;
    const int t = threadIdx.x;
    const int* ab = adj + (size_t)b * Nn * Nn;
#pragma unroll 4
    for (int r = 0; r < 32; r++) s[r][t] = ab[(size_t)(i0 + r) * Nn + j0 + t];
    __syncthreads();
    const int jg = j0 + t;
    unsigned w = 0;
#pragma unroll
    for (int r = 0; r < 32; r++)
        if (s[r][t] != 0 || (i0 + r) == jg) w |= (1u << r);
    g_bitT[((size_t)b * Nn + jg) * (Nn / 32) + (i0 >> 5)] = w;
}

// ---------------------------------------------------------------------------
// projection GEMM via mma.sync: g_x = feat @ W  (3-term bf16)
// CTA: 64m x 64n, 8 k-stages of 64.  SMEM 32KB static.
// ---------------------------------------------------------------------------
__global__ __launch_bounds__(128) void proj_mma() {
    __shared__ __align__(1024) char sm[32768];
    const uint32_t smb = smem_u32(sm);
    const int t = threadIdx.x, lane = t & 31, w = t >> 5;
    const int m0 = blockIdx.x * 64, n0 = blockIdx.y * 64;
    float acc[8][4];
#pragma unroll
    for (int j = 0; j < 8; j++)
#pragma unroll
        for (int k = 0; k < 4; k++) acc[j][k] = 0.f;

    for (int kt = 0; kt < 8; kt++) {
        __syncthreads();
#pragma unroll
        for (int q = 0; q < 4; q++) {
            int g = t + 128 * q, r = g >> 3, bl = g & 7;
            unsigned off = swz(r, bl);
            size_t src = (size_t)(m0 + r) * Dd + kt * 64 + bl * 8;
            size_t srb = (size_t)(n0 + r) * Dd + kt * 64 + bl * 8;
            *(float4*)(sm + off)         = *(const float4*)&g_fhi[src];
            *(float4*)(sm + 8192 + off)  = *(const float4*)&g_flo[src];
            *(float4*)(sm + 16384 + off) = *(const float4*)&g_wthi[srb];
            *(float4*)(sm + 24576 + off) = *(const float4*)&g_wtlo[srb];
        }
        __syncthreads();
        warp_mma_16x64(acc, smb, smb + 8192, smb + 16384, smb + 24576, lane, 16 * w);
    }

    const int rb = lane >> 2, cq = (lane & 3) * 2;
    const int r0 = m0 + 16 * w + rb, r1 = r0 + 8;
#pragma unroll
    for (int nt = 0; nt < 8; nt++) {
        int c = n0 + nt * 8 + cq;
        *(float2*)&g_x[(size_t)r0 * HC + c] = make_float2(acc[nt][0], acc[nt][1]);
        *(float2*)&g_x[(size_t)r1 * HC + c] = make_float2(acc[nt][2], acc[nt][3]);
    }
}

// ---------------------------------------------------------------------------
// attention exp tables [B,H,N]
// ---------------------------------------------------------------------------
__global__ __launch_bounds__(256) void attn_prep(const float* __restrict__ att_src,
                                                 const float* __restrict__ att_dst) {
    __shared__ float s_as[HC], s_ad[HC];
    for (int i = threadIdx.x; i < HC; i += blockDim.x) { s_as[i] = att_src[i]; s_ad[i] = att_dst[i]; }
    __syncthreads();
    int tid = blockIdx.x * 256 + threadIdx.x;
    int h = tid & 7, bn = tid >> 3, b = bn >> 11, n = bn & 2047;
    const float* xr = g_x + (size_t)bn * HC + h * Cc;
    float a = 0.f, d = 0.f;
#pragma unroll
    for (int c = 0; c < Cc; c += 4) {
        float4 xv = *(const float4*)&xr[c];
        float4 sv = *(const float4*)&s_as[h * Cc + c];
        float4 dv = *(const float4*)&s_ad[h * Cc + c];
        a += xv.x * sv.x + xv.y * sv.y + xv.z * sv.z + xv.w * sv.w;
        d += xv.x * dv.x + xv.y * dv.y + xv.z * dv.z + xv.w * dv.w;
    }
    int o = (b * Hh + h) * Nn + n;
    g_EAH[o]  = expf(a);        g_EA2H[o] = expf(0.2f * a);
    g_EBH[o]  = expf(d);        g_EB2H[o] = expf(0.2f * d);
}

// ---------------------------------------------------------------------------
// transpose x -> xT[b][h][c][i] bf16 hi/lo
// ---------------------------------------------------------------------------
__global__ __launch_bounds__(256) void transp_kernel() {
    __shared__ float s[32][65];
    const int b = blockIdx.z, h = blockIdx.y, i0 = blockIdx.x * 32, t = threadIdx.x;
#pragma unroll
    for (int q = 0; q < 8; q++) {
        int idx = t + 256 * q, r = idx >> 6, cc = idx & 63;
        s[r][cc] = g_x[(((size_t)b * Nn + i0 + r) * Hh + h) * Cc + cc];
    }
    __syncthreads();
#pragma unroll
    for (int q = 0; q < 8; q++) {
        int idx = t + 256 * q, cc = idx >> 5, ii = idx & 31;
        float v = s[ii][cc];
        __nv_bfloat16 hi = __float2bfloat16(v);
        __nv_bfloat16 lo = __float2bfloat16(v - __bfloat162float(hi));
        size_t o = (((size_t)b * Hh + h) * Cc + cc) * Nn + i0 + ii;
        g_xThi[o] = hi; g_xTlo[o] = lo;
    }
}

// ---------------------------------------------------------------------------
// fused masked-softmax aggregation via mma.sync
// CTA = (h, 64-j tile, b), 128 threads. SMEM static:
//   Phi@0 (8K) Plo@8192 Xhi@16384 (8K) Xlo@24576  + small tables
// Two threads per j row (each owns 32 of 64 i's).
// ---------------------------------------------------------------------------
__global__ __launch_bounds__(128) void gat_agg(const float* __restrict__ bias,
                                               float* __restrict__ out) {
    __shared__ __align__(1024) char sm[32768];
    __shared__ float sEA[64], sEA2[64];
    __shared__ float sDen[2][64];
    const uint32_t smb = smem_u32(sm);
    const int t = threadIdx.x, lane = t & 31, w = t >> 5;
    const int h = blockIdx.x, b = blockIdx.z, j0 = blockIdx.y * 64;
    const int bh = b * Hh + h;
    const int jrow = t & 63, half = t >> 6;
    const int jg = j0 + jrow;

    const float EBj  = g_EBH [bh * Nn + jg];
    const float EB2j = g_EB2H[bh * Nn + jg];
    const unsigned* bitrow = g_bitT + ((size_t)b * Nn + jg) * (Nn / 32);
    const __nv_bfloat16* xhi = g_xThi + (size_t)bh * Cc * Nn;
    const __nv_bfloat16* xlo = g_xTlo + (size_t)bh * Cc * Nn;

    float den = 0.f;
    float acc[8][4];
#pragma unroll
    for (int j = 0; j < 8; j++)
#pragma unroll
        for (int k = 0; k < 4; k++) acc[j][k] = 0.f;

    for (int ch = 0; ch < Nn / 64; ch++) {
        const int i0 = ch * 64;
        __syncthreads();               // prior MMA done before overwrite
        if (t < 64) {
            sEA [t] = g_EAH [bh * Nn + i0 + t];
            sEA2[t] = g_EA2H[bh * Nn + i0 + t];
        }
#pragma unroll
        for (int q = 0; q < 4; q++) {
            int g = t + 128 * q, r = g >> 3, bl = g & 7;
            unsigned off = swz(r, bl);
            *(float4*)(sm + 16384 + off) = *(const float4*)&xhi[(size_t)r * Nn + i0 + bl * 8];
            *(float4*)(sm + 24576 + off) = *(const float4*)&xlo[(size_t)r * Nn + i0 + bl * 8];
        }
        const unsigned mw = bitrow[ch * 2 + half];
        __syncthreads();

        // build own half-row of P: i in [32*half, 32*half+32)
#pragma unroll
        for (int ib = 0; ib < 4; ib++) {
            const int gran = half * 4 + ib;          // 16B granule (8 i's)
            const unsigned mb = mw >> (ib * 8);
            unsigned hp[4], lp[4];
#pragma unroll
            for (int p = 0; p < 2; p++) {
                float4 ea = ((const float4*)sEA )[gran * 2 + p];
                float4 e2 = ((const float4*)sEA2)[gran * 2 + p];
                float w0 = fmaxf(ea.x * EBj, e2.x * EB2j); if (!((mb >> (p * 4 + 0)) & 1)) w0 = 0.f;
                float w1 = fmaxf(ea.y * EBj, e2.y * EB2j); if (!((mb >> (p * 4 + 1)) & 1)) w1 = 0.f;
                float w2 = fmaxf(ea.z * EBj, e2.z * EB2j); if (!((mb >> (p * 4 + 2)) & 1)) w2 = 0.f;
                float w3 = fmaxf(ea.w * EBj, e2.w * EB2j); if (!((mb >> (p * 4 + 3)) & 1)) w3 = 0.f;
                den += (w0 + w1) + (w2 + w3);
                __nv_bfloat162 h01 = __floats2bfloat162_rn(w0, w1);
                __nv_bfloat162 h23 = __floats2bfloat162_rn(w2, w3);
                unsigned hb01 = *(unsigned*)&h01, hb23 = *(unsigned*)&h23;
                float l0 = w0 - __uint_as_float(hb01 << 16);
                float l1 = w1 - __uint_as_float(hb01 & 0xFFFF0000u);
                float l2 = w2 - __uint_as_float(hb23 << 16);
                float l3 = w3 - __uint_as_float(hb23 & 0xFFFF0000u);
                __nv_bfloat162 l01 = __floats2bfloat162_rn(l0, l1);
                __nv_bfloat162 l23 = __floats2bfloat162_rn(l2, l3);
                hp[2 * p] = hb01; hp[2 * p + 1] = hb23;
                lp[2 * p] = *(unsigned*)&l01; lp[2 * p + 1] = *(unsigned*)&l23;
            }
            unsigned off = swz((unsigned)jrow, (unsigned)gran);
            *(uint4*)(sm + off)        = make_uint4(hp[0], hp[1], hp[2], hp[3]);
            *(uint4*)(sm + 8192 + off) = make_uint4(lp[0], lp[1], lp[2], lp[3]);
        }
        __syncthreads();
        warp_mma_16x64(acc, smb, smb + 8192, smb + 16384, smb + 24576, lane, 16 * w);
    }

    sDen[half][jrow] = den;
    __syncthreads();

    // epilogue: normalize, +bias, ELU, store. Warp w owns rows 16w..16w+15.
    const int rb = lane >> 2, cq = (lane & 3) * 2;
    const int r0 = 16 * w + rb, r1 = r0 + 8;
    const float rd0 = 1.f / (sDen[0][r0] + sDen[1][r0]);
    const float rd1 = 1.f / (sDen[0][r1] + sDen[1][r1]);
#pragma unroll
    for (int nt = 0; nt < 8; nt++) {
        int c = h * Cc + nt * 8 + cq;
        float2 bv = *(const float2*)&bias[c];
        float v0 = acc[nt][0] * rd0 + bv.x;
        float v1 = acc[nt][1] * rd0 + bv.y;
        float v2 = acc[nt][2] * rd1 + bv.x;
        float v3 = acc[nt][3] * rd1 + bv.y;
        v0 = v0 > 0.f ? v0 : expf(v0) - 1.f;
        v1 = v1 > 0.f ? v1 : expf(v1) - 1.f;
        v2 = v2 > 0.f ? v2 : expf(v2) - 1.f;
        v3 = v3 > 0.f ? v3 : expf(v3) - 1.f;
        *(float2*)&out[(size_t)(b * Nn + j0 + r0) * HC + c] = make_float2(v0, v1);
        *(float2*)&out[(size_t)(b * Nn + j0 + r1) * HC + c] = make_float2(v2, v3);
    }
}

// ---------------------------------------------------------------------------
extern "C" void kernel_launch(void* const* d_in, const int* in_sizes, int n_in,
                              void* d_out, int out_size) {
    const float* feat    = (const float*)d_in[0];
    const int*   adj     = (const int*)  d_in[1];
    const float* W       = (const float*)d_in[2];
    const float* att_src = (const float*)d_in[3];
    const float* att_dst = (const float*)d_in[4];
    const float* bias    = (const float*)d_in[5];
    float* out = (float*)d_out;

    decomp_feat<<<(Bb * Nn * Dd) / 4 / 256, 256>>>(feat);
    decomp_wt<<<dim3(Dd / 32, HC / 32), 256>>>(W);
    pack_adj<<<dim3(64, 8, 4), 256>>>(adj);
    proj_mma<<<dim3(128, 8), 128>>>();
    attn_prep<<<(Bb * Nn * Hh) / 256, 256>>>(att_src, att_dst);
    transp_kernel<<<dim3(64, 8, 4), 256>>>();
    gat_agg<<<dim3(Hh, Nn / 64, Bb), 128>>>(bias, out);
}

// round 5
// speedup vs baseline: 2.4759x; 1.2169x over previous
#include <cuda_runtime.h>
#include <cuda_bf16.h>
#include <cuda_fp16.h>
#include <cstdint>

#define Bb 4
#define Nn 2048
#define Dd 512
#define Hh 8
#define Cc 64
#define HC 512

// ---------------- device scratch ----------------
__device__ float g_x[(size_t)Bb * Nn * HC];                 // [B,N,H,C] fp32
__device__ float g_EAH [Bb * Hh * Nn];                      // exp(a_src)   [B,H,N]
__device__ float g_EA2H[Bb * Hh * Nn];                      // exp(.2 a_src)
__device__ float g_EBH [Bb * Hh * Nn];                      // exp(a_dst)
__device__ float g_EB2H[Bb * Hh * Nn];
__device__ unsigned g_bitT[(size_t)Bb * Nn * (Nn / 32)];    // mask^T incl self-loops
__device__ __align__(16) __half g_xTh[(size_t)Bb * Hh * Cc * Nn];   // [B,H,C,N] fp16
__device__ __align__(16) __nv_bfloat16 g_fhi[(size_t)Bb * Nn * Dd]; // feat hi
__device__ __align__(16) __nv_bfloat16 g_flo[(size_t)Bb * Nn * Dd];
__device__ __align__(16) __nv_bfloat16 g_wthi[HC * Dd];             // W^T [n][k]
__device__ __align__(16) __nv_bfloat16 g_wtlo[HC * Dd];

// ---------------- helpers ----------------
__device__ __forceinline__ uint32_t smem_u32(const void* p) {
    uint32_t a;
    asm("{ .reg .u64 t; cvta.to.shared.u64 t, %1; cvt.u32.u64 %0, t; }" : "=r"(a) : "l"(p));
    return a;
}
__device__ __forceinline__ unsigned swz(unsigned r, unsigned kb) {
    return r * 128u + ((kb ^ (r & 7u)) << 4);
}
__device__ __forceinline__ void ldsm4(uint32_t addr, unsigned& r0, unsigned& r1,
                                      unsigned& r2, unsigned& r3) {
    asm volatile("ldmatrix.sync.aligned.m8n8.x4.shared.b16 {%0,%1,%2,%3}, [%4];"
                 : "=r"(r0), "=r"(r1), "=r"(r2), "=r"(r3) : "r"(addr));
}
__device__ __forceinline__ void mma4bf(float* c, const unsigned a[4], unsigned b0, unsigned b1) {
    asm volatile("mma.sync.aligned.m16n8k16.row.col.f32.bf16.bf16.f32 "
                 "{%0,%1,%2,%3}, {%4,%5,%6,%7}, {%8,%9}, {%0,%1,%2,%3};"
                 : "+f"(c[0]), "+f"(c[1]), "+f"(c[2]), "+f"(c[3])
                 : "r"(a[0]), "r"(a[1]), "r"(a[2]), "r"(a[3]), "r"(b0), "r"(b1));
}
__device__ __forceinline__ void mma4h(float* c, const unsigned a[4], unsigned b0, unsigned b1) {
    asm volatile("mma.sync.aligned.m16n8k16.row.col.f32.f16.f16.f32 "
                 "{%0,%1,%2,%3}, {%4,%5,%6,%7}, {%8,%9}, {%0,%1,%2,%3};"
                 : "+f"(c[0]), "+f"(c[1]), "+f"(c[2]), "+f"(c[3])
                 : "r"(a[0]), "r"(a[1]), "r"(a[2]), "r"(a[3]), "r"(b0), "r"(b1));
}

// ---------------------------------------------------------------------------
// decompose feat -> hi/lo bf16
// ---------------------------------------------------------------------------
__global__ __launch_bounds__(256) void decomp_feat(const float* __restrict__ f) {
    size_t idx = (size_t)blockIdx.x * 256 + threadIdx.x;
    float4 v = ((const float4*)f)[idx];
    __nv_bfloat162 h01 = __floats2bfloat162_rn(v.x, v.y);
    __nv_bfloat162 h23 = __floats2bfloat162_rn(v.z, v.w);
    unsigned hb0 = *(unsigned*)&h01, hb1 = *(unsigned*)&h23;
    float r0 = v.x - __uint_as_float(hb0 << 16);
    float r1 = v.y - __uint_as_float(hb0 & 0xFFFF0000u);
    float r2 = v.z - __uint_as_float(hb1 << 16);
    float r3 = v.w - __uint_as_float(hb1 & 0xFFFF0000u);
    __nv_bfloat162 l01 = __floats2bfloat162_rn(r0, r1);
    __nv_bfloat162 l23 = __floats2bfloat162_rn(r2, r3);
    ((uint2*)g_fhi)[idx] = make_uint2(hb0, hb1);
    ((uint2*)g_flo)[idx] = make_uint2(*(unsigned*)&l01, *(unsigned*)&l23);
}

// ---------------------------------------------------------------------------
// W [k][n] -> W^T hi/lo [n][k]
// ---------------------------------------------------------------------------
__global__ __launch_bounds__(256) void decomp_wt(const float* __restrict__ Wm) {
    __shared__ float s[32][33];
    const int k0 = blockIdx.x * 32, n0 = blockIdx.y * 32;
    const int t = threadIdx.x, r = t >> 5, c = t & 31;
#pragma unroll
    for (int q = 0; q < 4; q++)
        s[r + 8 * q][c] = Wm[(size_t)(k0 + r + 8 * q) * HC + n0 + c];
    __syncthreads();
#pragma unroll
    for (int q = 0; q < 4; q++) {
        int n = r + 8 * q;
        float v = s[c][n];
        __nv_bfloat16 hi = __float2bfloat16(v);
        __nv_bfloat16 lo = __float2bfloat16(v - __bfloat162float(hi));
        g_wthi[(size_t)(n0 + n) * Dd + k0 + c] = hi;
        g_wtlo[(size_t)(n0 + n) * Dd + k0 + c] = lo;
    }
}

// ---------------------------------------------------------------------------
// adjacency -> transposed bitmask (with self-loops)
// ---------------------------------------------------------------------------
__global__ __launch_bounds__(256) void pack_adj(const int* __restrict__ adj) {
    __shared__ int s[32][256];
    const int b = blockIdx.z, i0 = blockIdx.x * 32, j0 = blockIdx.y * 256;
    const int t = threadIdx.x;
    const int* ab = adj + (size_t)b * Nn * Nn;
#pragma unroll 4
    for (int r = 0; r < 32; r++) s[r][t] = ab[(size_t)(i0 + r) * Nn + j0 + t];
    __syncthreads();
    const int jg = j0 + t;
    unsigned w = 0;
#pragma unroll
    for (int r = 0; r < 32; r++)
        if (s[r][t] != 0 || (i0 + r) == jg) w |= (1u << r);
    g_bitT[((size_t)b * Nn + jg) * (Nn / 32) + (i0 >> 5)] = w;
}

// ---------------------------------------------------------------------------
// projection GEMM: g_x = feat @ W, bf16 3-term. CTA 128m x 64n, 4 warps,
// 32 rows/warp. SMEM: Ahi@0 16K | Alo@16K | Bhi@32K 8K | Blo@40K = 48K.
// ---------------------------------------------------------------------------
__global__ __launch_bounds__(128) void proj_mma() {
    __shared__ __align__(1024) char sm[49152];
    const uint32_t smb = smem_u32(sm);
    const int t = threadIdx.x, lane = t & 31, w = t >> 5;
    const int m0 = blockIdx.x * 128, n0 = blockIdx.y * 64;
    float acc[2][8][4];
#pragma unroll
    for (int i = 0; i < 2; i++)
#pragma unroll
        for (int j = 0; j < 8; j++)
#pragma unroll
            for (int k = 0; k < 4; k++) acc[i][j][k] = 0.f;

    for (int kt = 0; kt < 8; kt++) {
        __syncthreads();
#pragma unroll
        for (int q = 0; q < 8; q++) {          // A tile 128 rows
            int g = t + 128 * q, r = g >> 3, bl = g & 7;
            unsigned off = swz(r, bl);
            size_t src = (size_t)(m0 + r) * Dd + kt * 64 + bl * 8;
            *(float4*)(sm + off)        = *(const float4*)&g_fhi[src];
            *(float4*)(sm + 16384 + off) = *(const float4*)&g_flo[src];
        }
#pragma unroll
        for (int q = 0; q < 4; q++) {          // B tile 64 rows
            int g = t + 128 * q, r = g >> 3, bl = g & 7;
            unsigned off = swz(r, bl);
            size_t srb = (size_t)(n0 + r) * Dd + kt * 64 + bl * 8;
            *(float4*)(sm + 32768 + off) = *(const float4*)&g_wthi[srb];
            *(float4*)(sm + 40960 + off) = *(const float4*)&g_wtlo[srb];
        }
        __syncthreads();
#pragma unroll
        for (int ks = 0; ks < 4; ks++) {
            unsigned ah[2][4], al[2][4];
#pragma unroll
            for (int mt = 0; mt < 2; mt++) {
                unsigned offA = swz(32 * w + 16 * mt + (lane & 15), ks * 2 + (lane >> 4));
                ldsm4(smb + offA, ah[mt][0], ah[mt][1], ah[mt][2], ah[mt][3]);
                ldsm4(smb + 16384 + offA, al[mt][0], al[mt][1], al[mt][2], al[mt][3]);
            }
            unsigned brow = (lane & 7) + ((lane >> 4) << 3);
            unsigned bkb = ks * 2 + ((lane >> 3) & 1);
#pragma unroll
            for (int np = 0; np < 4; np++) {
                unsigned off = swz(brow + np * 16, bkb);
                unsigned h0, h1, h2, h3, l0, l1, l2, l3;
                ldsm4(smb + 32768 + off, h0, h1, h2, h3);
                ldsm4(smb + 40960 + off, l0, l1, l2, l3);
#pragma unroll
                for (int mt = 0; mt < 2; mt++) {
                    mma4bf(acc[mt][2 * np],     ah[mt], h0, h1);
                    mma4bf(acc[mt][2 * np],     ah[mt], l0, l1);
                    mma4bf(acc[mt][2 * np],     al[mt], h0, h1);
                    mma4bf(acc[mt][2 * np + 1], ah[mt], h2, h3);
                    mma4bf(acc[mt][2 * np + 1], ah[mt], l2, l3);
                    mma4bf(acc[mt][2 * np + 1], al[mt], h2, h3);
                }
            }
        }
    }

    const int rb = lane >> 2, cq = (lane & 3) * 2;
#pragma unroll
    for (int mt = 0; mt < 2; mt++) {
        int r0 = m0 + 32 * w + 16 * mt + rb, r1 = r0 + 8;
#pragma unroll
        for (int nt = 0; nt < 8; nt++) {
            int c = n0 + nt * 8 + cq;
            *(float2*)&g_x[(size_t)r0 * HC + c] = make_float2(acc[mt][nt][0], acc[mt][nt][1]);
            *(float2*)&g_x[(size_t)r1 * HC + c] = make_float2(acc[mt][nt][2], acc[mt][nt][3]);
        }
    }
}

// ---------------------------------------------------------------------------
// fused transpose + attention tables: x -> xT[b][h][c][i] fp16, exp tables
// ---------------------------------------------------------------------------
__global__ __launch_bounds__(256) void transp_attn(const float* __restrict__ att_src,
                                                   const float* __restrict__ att_dst) {
    __shared__ float s[32][65];
    const int b = blockIdx.z, h = blockIdx.y, i0 = blockIdx.x * 32, t = threadIdx.x;
#pragma unroll
    for (int q = 0; q < 8; q++) {
        int idx = t + 256 * q, r = idx >> 6, cc = idx & 63;
        s[r][cc] = g_x[(((size_t)b * Nn + i0 + r) * Hh + h) * Cc + cc];
    }
    __syncthreads();

    // attention dots: 8 threads per row
    {
        int r = t >> 3, sub = t & 7;
        float a = 0.f, d = 0.f;
#pragma unroll
        for (int q = 0; q < 2; q++) {
            int c = sub * 8 + q * 4;
            float4 sv = *(const float4*)&att_src[h * Cc + c];
            float4 dv = *(const float4*)&att_dst[h * Cc + c];
            a += s[r][c] * sv.x + s[r][c + 1] * sv.y + s[r][c + 2] * sv.z + s[r][c + 3] * sv.w;
            d += s[r][c] * dv.x + s[r][c + 1] * dv.y + s[r][c + 2] * dv.z + s[r][c + 3] * dv.w;
        }
#pragma unroll
        for (int o = 4; o >= 1; o >>= 1) {
            a += __shfl_xor_sync(0xffffffffu, a, o);
            d += __shfl_xor_sync(0xffffffffu, d, o);
        }
        if (sub == 0) {
            int o = (b * Hh + h) * Nn + i0 + r;
            g_EAH [o] = expf(a);        g_EA2H[o] = expf(0.2f * a);
            g_EBH [o] = expf(d);        g_EB2H[o] = expf(0.2f * d);
        }
    }

    // transposed fp16 write
#pragma unroll
    for (int q = 0; q < 8; q++) {
        int idx = t + 256 * q, cc = idx >> 5, ii = idx & 31;
        g_xTh[(((size_t)b * Hh + h) * Cc + cc) * Nn + i0 + ii] = __float2half(s[ii][cc]);
    }
}

// ---------------------------------------------------------------------------
// fused masked-softmax aggregation, fp16: P 2-term, X 1-term.
// CTA = (h, 128-j tile, b), 128 threads, 4 warps, 32 rows/warp.
// SMEM: Phi@0 16K | Plo@16K | X@32K 8K  (40K) + tables.
// ---------------------------------------------------------------------------
__global__ __launch_bounds__(128) void gat_agg(const float* __restrict__ bias,
                                               float* __restrict__ out) {
    __shared__ __align__(1024) char sm[40960];
    __shared__ float sEA[64], sEA2[64], sDen[128];
    const uint32_t smb = smem_u32(sm);
    const int t = threadIdx.x, lane = t & 31, w = t >> 5;
    const int h = blockIdx.x, b = blockIdx.z, j0 = blockIdx.y * 128;
    const int bh = b * Hh + h;
    const int jg = j0 + t;                     // 1 thread per j row

    const float EBj  = g_EBH [bh * Nn + jg];
    const float EB2j = g_EB2H[bh * Nn + jg];
    const unsigned* bitrow = g_bitT + ((size_t)b * Nn + jg) * (Nn / 32);
    const __half* xh = g_xTh + (size_t)bh * Cc * Nn;

    float den = 0.f;
    float acc[2][8][4];
#pragma unroll
    for (int i = 0; i < 2; i++)
#pragma unroll
        for (int j = 0; j < 8; j++)
#pragma unroll
            for (int k = 0; k < 4; k++) acc[i][j][k] = 0.f;

    for (int ch = 0; ch < Nn / 64; ch++) {
        const int i0 = ch * 64;
        __syncthreads();                       // prior MMA reads done
        if (t < 64) sEA [t]      = g_EAH [bh * Nn + i0 + t];
        else        sEA2[t - 64] = g_EA2H[bh * Nn + i0 + (t - 64)];
#pragma unroll
        for (int q = 0; q < 4; q++) {          // X tile: 64 rows x 128B fp16
            int g = t + 128 * q, r = g >> 3, bl = g & 7;
            *(float4*)(sm + 32768 + swz(r, bl)) =
                *(const float4*)&xh[(size_t)r * Nn + i0 + bl * 8];
        }
        const unsigned mw0 = bitrow[ch * 2], mw1 = bitrow[ch * 2 + 1];
        __syncthreads();                       // X + tables visible

        // build own P row (j = jg), 64 i's, fp16 hi/lo
#pragma unroll
        for (int ib = 0; ib < 8; ib++) {
            const unsigned mb = ((ib < 4) ? mw0 : mw1) >> ((ib & 3) * 8);
            float4 ea0 = ((const float4*)sEA )[ib * 2];
            float4 ea1 = ((const float4*)sEA )[ib * 2 + 1];
            float4 e20 = ((const float4*)sEA2)[ib * 2];
            float4 e21 = ((const float4*)sEA2)[ib * 2 + 1];
            float wv[8];
            wv[0] = fmaxf(ea0.x * EBj, e20.x * EB2j); if (!((mb >> 0) & 1)) wv[0] = 0.f;
            wv[1] = fmaxf(ea0.y * EBj, e20.y * EB2j); if (!((mb >> 1) & 1)) wv[1] = 0.f;
            wv[2] = fmaxf(ea0.z * EBj, e20.z * EB2j); if (!((mb >> 2) & 1)) wv[2] = 0.f;
            wv[3] = fmaxf(ea0.w * EBj, e20.w * EB2j); if (!((mb >> 3) & 1)) wv[3] = 0.f;
            wv[4] = fmaxf(ea1.x * EBj, e21.x * EB2j); if (!((mb >> 4) & 1)) wv[4] = 0.f;
            wv[5] = fmaxf(ea1.y * EBj, e21.y * EB2j); if (!((mb >> 5) & 1)) wv[5] = 0.f;
            wv[6] = fmaxf(ea1.z * EBj, e21.z * EB2j); if (!((mb >> 6) & 1)) wv[6] = 0.f;
            wv[7] = fmaxf(ea1.w * EBj, e21.w * EB2j); if (!((mb >> 7) & 1)) wv[7] = 0.f;
            den += ((wv[0] + wv[1]) + (wv[2] + wv[3])) + ((wv[4] + wv[5]) + (wv[6] + wv[7]));
            unsigned hp[4], lp[4];
#pragma unroll
            for (int p = 0; p < 4; p++) {
                __half2 hh = __floats2half2_rn(wv[2 * p], wv[2 * p + 1]);
                hp[p] = *(unsigned*)&hh;
                float2 hf = __half22float2(hh);
                __half2 ll = __floats2half2_rn(wv[2 * p] - hf.x, wv[2 * p + 1] - hf.y);
                lp[p] = *(unsigned*)&ll;
            }
            unsigned off = swz((unsigned)t, (unsigned)ib);
            *(uint4*)(sm + off)         = make_uint4(hp[0], hp[1], hp[2], hp[3]);
            *(uint4*)(sm + 16384 + off) = make_uint4(lp[0], lp[1], lp[2], lp[3]);
        }
        __syncwarp();                          // P rows 32w..32w+31 are warp-private

        // MMA: warp w, rows 32w..32w+31, 2 terms (PhX, PlX)
#pragma unroll
        for (int ks = 0; ks < 4; ks++) {
            unsigned ah[2][4], al[2][4];
#pragma unroll
            for (int mt = 0; mt < 2; mt++) {
                unsigned offA = swz(32 * w + 16 * mt + (lane & 15), ks * 2 + (lane >> 4));
                ldsm4(smb + offA, ah[mt][0], ah[mt][1], ah[mt][2], ah[mt][3]);
                ldsm4(smb + 16384 + offA, al[mt][0], al[mt][1], al[mt][2], al[mt][3]);
            }
            unsigned brow = (lane & 7) + ((lane >> 4) << 3);
            unsigned bkb = ks * 2 + ((lane >> 3) & 1);
#pragma unroll
            for (int np = 0; np < 4; np++) {
                unsigned b0, b1, b2, b3;
                ldsm4(smb + 32768 + swz(brow + np * 16, bkb), b0, b1, b2, b3);
#pragma unroll
                for (int mt = 0; mt < 2; mt++) {
                    mma4h(acc[mt][2 * np],     ah[mt], b0, b1);
                    mma4h(acc[mt][2 * np],     al[mt], b0, b1);
                    mma4h(acc[mt][2 * np + 1], ah[mt], b2, b3);
                    mma4h(acc[mt][2 * np + 1], al[mt], b2, b3);
                }
            }
        }
    }

    sDen[t] = den;
    __syncthreads();

    // epilogue: normalize, +bias, ELU, store
    const int rb = lane >> 2, cq = (lane & 3) * 2;
#pragma unroll
    for (int mt = 0; mt < 2; mt++) {
        int r0 = 32 * w + 16 * mt + rb, r1 = r0 + 8;
        float rd0 = 1.f / sDen[r0], rd1 = 1.f / sDen[r1];
#pragma unroll
        for (int nt = 0; nt < 8; nt++) {
            int c = h * Cc + nt * 8 + cq;
            float2 bv = *(const float2*)&bias[c];
            float v0 = acc[mt][nt][0] * rd0 + bv.x;
            float v1 = acc[mt][nt][1] * rd0 + bv.y;
            float v2 = acc[mt][nt][2] * rd1 + bv.x;
            float v3 = acc[mt][nt][3] * rd1 + bv.y;
            v0 = v0 > 0.f ? v0 : expf(v0) - 1.f;
            v1 = v1 > 0.f ? v1 : expf(v1) - 1.f;
            v2 = v2 > 0.f ? v2 : expf(v2) - 1.f;
            v3 = v3 > 0.f ? v3 : expf(v3) - 1.f;
            *(float2*)&out[(size_t)(b * Nn + j0 + r0) * HC + c] = make_float2(v0, v1);
            *(float2*)&out[(size_t)(b * Nn + j0 + r1) * HC + c] = make_float2(v2, v3);
        }
    }
}

// ---------------------------------------------------------------------------
extern "C" void kernel_launch(void* const* d_in, const int* in_sizes, int n_in,
                              void* d_out, int out_size) {
    const float* feat    = (const float*)d_in[0];
    const int*   adj     = (const int*)  d_in[1];
    const float* W       = (const float*)d_in[2];
    const float* att_src = (const float*)d_in[3];
    const float* att_dst = (const float*)d_in[4];
    const float* bias    = (const float*)d_in[5];
    float* out = (float*)d_out;

    decomp_feat<<<(Bb * Nn * Dd) / 4 / 256, 256>>>(feat);
    decomp_wt<<<dim3(Dd / 32, HC / 32), 256>>>(W);
    pack_adj<<<dim3(64, 8, 4), 256>>>(adj);
    proj_mma<<<dim3(64, 8), 128>>>();
    transp_attn<<<dim3(64, 8, 4), 256>>>(att_src, att_dst);
    gat_agg<<<dim3(Hh, Nn / 128, Bb), 128>>>(bias, out);
}

// round 8
// speedup vs baseline: 3.7186x; 1.5019x over previous
#include <cuda_runtime.h>
#include <cuda_bf16.h>
#include <cuda_fp16.h>
#include <cstdint>

#define Bb 4
#define Nn 2048
#define Dd 512
#define Hh 8
#define Cc 64
#define HC 512

// ---------------- device scratch ----------------
__device__ float g_x[(size_t)Bb * Nn * HC];                 // [B,N,H,C] fp32
__device__ float g_EAH [Bb * Hh * Nn];
__device__ float g_EA2H[Bb * Hh * Nn];
__device__ float g_EBH [Bb * Hh * Nn];
__device__ float g_EB2H[Bb * Hh * Nn];
__device__ unsigned g_bitT[(size_t)Bb * Nn * (Nn / 32)];
__device__ __align__(16) __half g_xTh[(size_t)Bb * Hh * Cc * Nn];   // [B,H,C,N] fp16
__device__ __align__(16) __nv_bfloat16 g_fhi[(size_t)Bb * Nn * Dd];
__device__ __align__(16) __nv_bfloat16 g_flo[(size_t)Bb * Nn * Dd];
__device__ __align__(16) __nv_bfloat16 g_wthi[HC * Dd];             // W^T [n][k]
__device__ __align__(16) __nv_bfloat16 g_wtlo[HC * Dd];

// ---------------- helpers ----------------
__device__ __forceinline__ uint32_t smem_u32(const void* p) {
    uint32_t a;
    asm("{ .reg .u64 t; cvta.to.shared.u64 t, %1; cvt.u32.u64 %0, t; }" : "=r"(a) : "l"(p));
    return a;
}
__device__ __forceinline__ unsigned swz(unsigned r, unsigned kb) {
    return r * 128u + ((kb ^ (r & 7u)) << 4);
}
__device__ __forceinline__ void ldsm4(uint32_t addr, unsigned& r0, unsigned& r1,
                                      unsigned& r2, unsigned& r3) {
    asm volatile("ldmatrix.sync.aligned.m8n8.x4.shared.b16 {%0,%1,%2,%3}, [%4];"
                 : "=r"(r0), "=r"(r1), "=r"(r2), "=r"(r3) : "r"(addr));
}
__device__ __forceinline__ void mma4bf(float* c, const unsigned a[4], unsigned b0, unsigned b1) {
    asm volatile("mma.sync.aligned.m16n8k16.row.col.f32.bf16.bf16.f32 "
                 "{%0,%1,%2,%3}, {%4,%5,%6,%7}, {%8,%9}, {%0,%1,%2,%3};"
                 : "+f"(c[0]), "+f"(c[1]), "+f"(c[2]), "+f"(c[3])
                 : "r"(a[0]), "r"(a[1]), "r"(a[2]), "r"(a[3]), "r"(b0), "r"(b1));
}
__device__ __forceinline__ void mma4h(float* c, const unsigned a[4], unsigned b0, unsigned b1) {
    asm volatile("mma.sync.aligned.m16n8k16.row.col.f32.f16.f16.f32 "
                 "{%0,%1,%2,%3}, {%4,%5,%6,%7}, {%8,%9}, {%0,%1,%2,%3};"
                 : "+f"(c[0]), "+f"(c[1]), "+f"(c[2]), "+f"(c[3])
                 : "r"(a[0]), "r"(a[1]), "r"(a[2]), "r"(a[3]), "r"(b0), "r"(b1));
}
#define CP16(dst, src) \
    asm volatile("cp.async.cg.shared.global [%0], [%1], 16;" :: "r"(dst), "l"(src))
#define CP_COMMIT() asm volatile("cp.async.commit_group;" ::: "memory")
#define CP_WAIT0()  asm volatile("cp.async.wait_group 0;" ::: "memory")
#define CP_WAIT1()  asm volatile("cp.async.wait_group 1;" ::: "memory")

// ---------------------------------------------------------------------------
// decompose feat -> hi/lo bf16
// ---------------------------------------------------------------------------
__global__ __launch_bounds__(256) void decomp_feat(const float* __restrict__ f) {
    size_t idx = (size_t)blockIdx.x * 256 + threadIdx.x;
    float4 v = ((const float4*)f)[idx];
    __nv_bfloat162 h01 = __floats2bfloat162_rn(v.x, v.y);
    __nv_bfloat162 h23 = __floats2bfloat162_rn(v.z, v.w);
    unsigned hb0 = *(unsigned*)&h01, hb1 = *(unsigned*)&h23;
    float r0 = v.x - __uint_as_float(hb0 << 16);
    float r1 = v.y - __uint_as_float(hb0 & 0xFFFF0000u);
    float r2 = v.z - __uint_as_float(hb1 << 16);
    float r3 = v.w - __uint_as_float(hb1 & 0xFFFF0000u);
    __nv_bfloat162 l01 = __floats2bfloat162_rn(r0, r1);
    __nv_bfloat162 l23 = __floats2bfloat162_rn(r2, r3);
    ((uint2*)g_fhi)[idx] = make_uint2(hb0, hb1);
    ((uint2*)g_flo)[idx] = make_uint2(*(unsigned*)&l01, *(unsigned*)&l23);
}

// ---------------------------------------------------------------------------
// W [k][n] -> W^T hi/lo [n][k]
// ---------------------------------------------------------------------------
__global__ __launch_bounds__(256) void decomp_wt(const float* __restrict__ Wm) {
    __shared__ float s[32][33];
    const int k0 = blockIdx.x * 32, n0 = blockIdx.y * 32;
    const int t = threadIdx.x, r = t >> 5, c = t & 31;
#pragma unroll
    for (int q = 0; q < 4; q++)
        s[r + 8 * q][c] = Wm[(size_t)(k0 + r + 8 * q) * HC + n0 + c];
    __syncthreads();
#pragma unroll
    for (int q = 0; q < 4; q++) {
        int n = r + 8 * q;
        float v = s[c][n];
        __nv_bfloat16 hi = __float2bfloat16(v);
        __nv_bfloat16 lo = __float2bfloat16(v - __bfloat162float(hi));
        g_wthi[(size_t)(n0 + n) * Dd + k0 + c] = hi;
        g_wtlo[(size_t)(n0 + n) * Dd + k0 + c] = lo;
    }
}

// ---------------------------------------------------------------------------
// adjacency -> transposed bitmask (with self-loops)
// ---------------------------------------------------------------------------
__global__ __launch_bounds__(256) void pack_adj(const int* __restrict__ adj) {
    __shared__ int s[32][256];
    const int b = blockIdx.z, i0 = blockIdx.x * 32, j0 = blockIdx.y * 256;
    const int t = threadIdx.x;
    const int* ab = adj + (size_t)b * Nn * Nn;
#pragma unroll 4
    for (int r = 0; r < 32; r++) s[r][t] = ab[(size_t)(i0 + r) * Nn + j0 + t];
    __syncthreads();
    const int jg = j0 + t;
    unsigned w = 0;
#pragma unroll
    for (int r = 0; r < 32; r++)
        if (s[r][t] != 0 || (i0 + r) == jg) w |= (1u << r);
    g_bitT[((size_t)b * Nn + jg) * (Nn / 32) + (i0 >> 5)] = w;
}

// ---------------------------------------------------------------------------
// projection GEMM, double-buffered cp.async, BK=32 (granule-half trick).
// CTA 128m x 64n. SMEM 48K: Ahi[0,16K) Alo[16K) Bhi[32K,8K) Blo[40K).
// Stage parity p picks granules [4p,4p+4) within 128B-pitch SW128 rows.
// ---------------------------------------------------------------------------
__global__ __launch_bounds__(128) void proj_mma() {
    __shared__ __align__(1024) char sm[49152];
    const uint32_t smb = smem_u32(sm);
    const int t = threadIdx.x, lane = t & 31, w = t >> 5;
    const int m0 = blockIdx.x * 128, n0 = blockIdx.y * 64;

    float acc[2][8][4];
#pragma unroll
    for (int i = 0; i < 2; i++)
#pragma unroll
        for (int j = 0; j < 8; j++)
#pragma unroll
            for (int k = 0; k < 4; k++) acc[i][j][k] = 0.f;

    // stage loader: p = kt&1
    auto load_stage = [&](int kt) {
        const int p = kt & 1;
#pragma unroll
        for (int q = 0; q < 4; q++) {                 // A: 512 units
            int u = t + 128 * q, r = u >> 2, gr = u & 3;
            unsigned off = swz(r, p * 4 + gr);
            const __nv_bfloat16* sh = &g_fhi[(size_t)(m0 + r) * Dd + kt * 32 + gr * 8];
            const __nv_bfloat16* sl = &g_flo[(size_t)(m0 + r) * Dd + kt * 32 + gr * 8];
            CP16(smb + off, sh);
            CP16(smb + 16384 + off, sl);
        }
#pragma unroll
        for (int q = 0; q < 2; q++) {                 // B: 256 units
            int u = t + 128 * q, r = u >> 2, gr = u & 3;
            unsigned off = swz(r, p * 4 + gr);
            const __nv_bfloat16* sh = &g_wthi[(size_t)(n0 + r) * Dd + kt * 32 + gr * 8];
            const __nv_bfloat16* sl = &g_wtlo[(size_t)(n0 + r) * Dd + kt * 32 + gr * 8];
            CP16(smb + 32768 + off, sh);
            CP16(smb + 40960 + off, sl);
        }
        CP_COMMIT();
    };

    load_stage(0);

#pragma unroll 1
    for (int kt = 0; kt < 16; kt++) {
        if (kt + 1 < 16) { load_stage(kt + 1); CP_WAIT1(); }
        else             { CP_WAIT0(); }
        __syncthreads();
        const int p = kt & 1;
#pragma unroll
        for (int ks = 0; ks < 2; ks++) {
            unsigned ah[2][4], al[2][4];
#pragma unroll
            for (int mt = 0; mt < 2; mt++) {
                unsigned offA = swz(32 * w + 16 * mt + (lane & 15),
                                    p * 4 + ks * 2 + (lane >> 4));
                ldsm4(smb + offA, ah[mt][0], ah[mt][1], ah[mt][2], ah[mt][3]);
                ldsm4(smb + 16384 + offA, al[mt][0], al[mt][1], al[mt][2], al[mt][3]);
            }
            unsigned brow = (lane & 7) + ((lane >> 4) << 3);
            unsigned bkb = p * 4 + ks * 2 + ((lane >> 3) & 1);
#pragma unroll
            for (int np = 0; np < 4; np++) {
                unsigned off = swz(brow + np * 16, bkb);
                unsigned h0, h1, h2, h3, l0, l1, l2, l3;
                ldsm4(smb + 32768 + off, h0, h1, h2, h3);
                ldsm4(smb + 40960 + off, l0, l1, l2, l3);
#pragma unroll
                for (int mt = 0; mt < 2; mt++) {
                    mma4bf(acc[mt][2 * np],     ah[mt], h0, h1);
                    mma4bf(acc[mt][2 * np],     ah[mt], l0, l1);
                    mma4bf(acc[mt][2 * np],     al[mt], h0, h1);
                    mma4bf(acc[mt][2 * np + 1], ah[mt], h2, h3);
                    mma4bf(acc[mt][2 * np + 1], ah[mt], l2, l3);
                    mma4bf(acc[mt][2 * np + 1], al[mt], h2, h3);
                }
            }
        }
        __syncthreads();
    }

    const int rb = lane >> 2, cq = (lane & 3) * 2;
#pragma unroll
    for (int mt = 0; mt < 2; mt++) {
        int r0 = m0 + 32 * w + 16 * mt + rb, r1 = r0 + 8;
#pragma unroll
        for (int nt = 0; nt < 8; nt++) {
            int c = n0 + nt * 8 + cq;
            *(float2*)&g_x[(size_t)r0 * HC + c] = make_float2(acc[mt][nt][0], acc[mt][nt][1]);
            *(float2*)&g_x[(size_t)r1 * HC + c] = make_float2(acc[mt][nt][2], acc[mt][nt][3]);
        }
    }
}

// ---------------------------------------------------------------------------
// fused transpose + attention tables
// ---------------------------------------------------------------------------
__global__ __launch_bounds__(256) void transp_attn(const float* __restrict__ att_src,
                                                   const float* __restrict__ att_dst) {
    __shared__ float s[32][65];
    const int b = blockIdx.z, h = blockIdx.y, i0 = blockIdx.x * 32, t = threadIdx.x;
#pragma unroll
    for (int q = 0; q < 8; q++) {
        int idx = t + 256 * q, r = idx >> 6, cc = idx & 63;
        s[r][cc] = g_x[(((size_t)b * Nn + i0 + r) * Hh + h) * Cc + cc];
    }
    __syncthreads();
    {
        int r = t >> 3, sub = t & 7;
        float a = 0.f, d = 0.f;
#pragma unroll
        for (int q = 0; q < 2; q++) {
            int c = sub * 8 + q * 4;
            float4 sv = *(const float4*)&att_src[h * Cc + c];
            float4 dv = *(const float4*)&att_dst[h * Cc + c];
            a += s[r][c] * sv.x + s[r][c + 1] * sv.y + s[r][c + 2] * sv.z + s[r][c + 3] * sv.w;
            d += s[r][c] * dv.x + s[r][c + 1] * dv.y + s[r][c + 2] * dv.z + s[r][c + 3] * dv.w;
        }
#pragma unroll
        for (int o = 4; o >= 1; o >>= 1) {
            a += __shfl_xor_sync(0xffffffffu, a, o);
            d += __shfl_xor_sync(0xffffffffu, d, o);
        }
        if (sub == 0) {
            int o = (b * Hh + h) * Nn + i0 + r;
            g_EAH [o] = expf(a);        g_EA2H[o] = expf(0.2f * a);
            g_EBH [o] = expf(d);        g_EB2H[o] = expf(0.2f * d);
        }
    }
#pragma unroll
    for (int q = 0; q < 8; q++) {
        int idx = t + 256 * q, cc = idx >> 5, ii = idx & 31;
        g_xTh[(((size_t)b * Hh + h) * Cc + cc) * Nn + i0 + ii] = __float2half(s[ii][cc]);
    }
}

// ---------------------------------------------------------------------------
// fused masked-softmax aggregation: P 1-term fp16, X 1-term fp16,
// den via ones-column MMA (consistent rounding). cp.async overlap:
// tables group waited before build, X group only before MMA.
// SMEM: P[0,16K) 128x128B | X[16K, 10K) 80x128B (rows 64..79 = ones/zeros)
// ---------------------------------------------------------------------------
__global__ __launch_bounds__(128) void gat_agg(const float* __restrict__ bias,
                                               float* __restrict__ out) {
    __shared__ __align__(1024) char sm[16384 + 10240];
    __shared__ __align__(16) float sEA[64], sEA2[64];
    const uint32_t smb = smem_u32(sm);
    const uint32_t xb  = smb + 16384;
    const int t = threadIdx.x, lane = t & 31, w = t >> 5;
    const int h = blockIdx.x, b = blockIdx.z, j0 = blockIdx.y * 128;
    const int bh = b * Hh + h;
    const int jg = j0 + t;

    const float EBj  = g_EBH [bh * Nn + jg];
    const float EB2j = g_EB2H[bh * Nn + jg];
    const unsigned* bitrow = g_bitT + ((size_t)b * Nn + jg) * (Nn / 32);
    const __half* xh = g_xTh + (size_t)bh * Cc * Nn;

    // ones/zeros rows 64..79 of X tile (written once)
    {
        int r = 64 + (t >> 3), gr = t & 7;
        unsigned v = (r == 64) ? 0x3C003C00u : 0u;
        *(uint4*)(sm + 16384 + swz(r, gr)) = make_uint4(v, v, v, v);
    }

    float acc[2][8][4];
    float accd[2][4];
#pragma unroll
    for (int i = 0; i < 2; i++) {
#pragma unroll
        for (int j = 0; j < 8; j++)
#pragma unroll
            for (int k = 0; k < 4; k++) acc[i][j][k] = 0.f;
#pragma unroll
        for (int k = 0; k < 4; k++) accd[i][k] = 0.f;
    }
    __syncthreads();

#pragma unroll 1
    for (int ch = 0; ch < Nn / 64; ch++) {
        const int i0 = ch * 64;
        // group 1: exp tables (small, needed by build)
        if (t < 32) {
            uint32_t dst; const float* src;
            if (t < 16) { dst = smem_u32(sEA)  + t * 16;        src = &g_EAH [bh * Nn + i0 + t * 4]; }
            else        { dst = smem_u32(sEA2) + (t - 16) * 16; src = &g_EA2H[bh * Nn + i0 + (t - 16) * 4]; }
            CP16(dst, src);
        }
        CP_COMMIT();
        // group 2: X tile (needed only by MMA)
#pragma unroll
        for (int q = 0; q < 4; q++) {
            int u = t + 128 * q, r = u >> 3, gr = u & 7;
            CP16(xb + swz(r, gr), xh + (size_t)r * Nn + i0 + gr * 8);
        }
        CP_COMMIT();
        CP_WAIT1();                 // tables landed; X may still be in flight
        __syncthreads();

        // build own P row (j = jg), 64 i's, fp16 (1 term)
        const uint2 mwp = *(const uint2*)(bitrow + ch * 2);
#pragma unroll
        for (int ib2 = 0; ib2 < 4; ib2++) {           // 16 i's per iter
            const unsigned mb = ((ib2 < 2) ? mwp.x : mwp.y) >> ((ib2 & 1) * 16);
            float wv[16];
#pragma unroll
            for (int q = 0; q < 4; q++) {
                float4 ea = ((const float4*)sEA )[ib2 * 4 + q];
                float4 e2 = ((const float4*)sEA2)[ib2 * 4 + q];
                float a0 = fmaxf(ea.x * EBj, e2.x * EB2j);
                float a1 = fmaxf(ea.y * EBj, e2.y * EB2j);
                float a2 = fmaxf(ea.z * EBj, e2.z * EB2j);
                float a3 = fmaxf(ea.w * EBj, e2.w * EB2j);
                wv[4 * q + 0] = ((mb >> (4 * q + 0)) & 1u) ? a0 : 0.f;
                wv[4 * q + 1] = ((mb >> (4 * q + 1)) & 1u) ? a1 : 0.f;
                wv[4 * q + 2] = ((mb >> (4 * q + 2)) & 1u) ? a2 : 0.f;
                wv[4 * q + 3] = ((mb >> (4 * q + 3)) & 1u) ? a3 : 0.f;
            }
            unsigned hp[8];
#pragma unroll
            for (int p = 0; p < 8; p++) {
                __half2 hh = __floats2half2_rn(wv[2 * p], wv[2 * p + 1]);
                hp[p] = *(unsigned*)&hh;
            }
            *(uint4*)(sm + swz((unsigned)t, ib2 * 2))     = make_uint4(hp[0], hp[1], hp[2], hp[3]);
            *(uint4*)(sm + swz((unsigned)t, ib2 * 2 + 1)) = make_uint4(hp[4], hp[5], hp[6], hp[7]);
        }
        CP_WAIT0();                 // X landed
        __syncthreads();            // P + X visible to all

        // MMA: warp w rows 32w..32w+31; 32 P.X MMAs + 8 den MMAs
#pragma unroll
        for (int ks = 0; ks < 4; ks++) {
            unsigned ah[2][4];
#pragma unroll
            for (int mt = 0; mt < 2; mt++) {
                unsigned offA = swz(32 * w + 16 * mt + (lane & 15), ks * 2 + (lane >> 4));
                ldsm4(smb + offA, ah[mt][0], ah[mt][1], ah[mt][2], ah[mt][3]);
            }
            unsigned brow = (lane & 7) + ((lane >> 4) << 3);
            unsigned bkb = ks * 2 + ((lane >> 3) & 1);
#pragma unroll
            for (int np = 0; np < 4; np++) {
                unsigned b0, b1, b2, b3;
                ldsm4(xb + swz(brow + np * 16, bkb), b0, b1, b2, b3);
                mma4h(acc[0][2 * np],     ah[0], b0, b1);
                mma4h(acc[1][2 * np],     ah[1], b0, b1);
                mma4h(acc[0][2 * np + 1], ah[0], b2, b3);
                mma4h(acc[1][2 * np + 1], ah[1], b2, b3);
            }
            unsigned d0, d1, d2, d3;
            ldsm4(xb + swz(64 + brow, bkb), d0, d1, d2, d3);
            mma4h(accd[0], ah[0], d0, d1);
            mma4h(accd[1], ah[1], d0, d1);
        }
        __syncthreads();            // MMA done before next chunk overwrites
    }

    // epilogue: den from ones column (col 64 lives in cq==0 threads)
    const int rb = lane >> 2, cq = (lane & 3) * 2;
#pragma unroll
    for (int mt = 0; mt < 2; mt++) {
        float dn0 = __shfl_sync(0xffffffffu, accd[mt][0], lane & 28);
        float dn1 = __shfl_sync(0xffffffffu, accd[mt][2], lane & 28);
        float rd0 = 1.f / dn0, rd1 = 1.f / dn1;
        int r0 = j0 + 32 * w + 16 * mt + rb, r1 = r0 + 8;
#pragma unroll
        for (int nt = 0; nt < 8; nt++) {
            int c = h * Cc + nt * 8 + cq;
            float2 bv = *(const float2*)&bias[c];
            float v0 = acc[mt][nt][0] * rd0 + bv.x;
            float v1 = acc[mt][nt][1] * rd0 + bv.y;
            float v2 = acc[mt][nt][2] * rd1 + bv.x;
            float v3 = acc[mt][nt][3] * rd1 + bv.y;
            v0 = v0 > 0.f ? v0 : expf(v0) - 1.f;
            v1 = v1 > 0.f ? v1 : expf(v1) - 1.f;
            v2 = v2 > 0.f ? v2 : expf(v2) - 1.f;
            v3 = v3 > 0.f ? v3 : expf(v3) - 1.f;
            *(float2*)&out[(size_t)(b * Nn + r0) * HC + c] = make_float2(v0, v1);
            *(float2*)&out[(size_t)(b * Nn + r1) * HC + c] = make_float2(v2, v3);
        }
    }
}

// ---------------------------------------------------------------------------
extern "C" void kernel_launch(void* const* d_in, const int* in_sizes, int n_in,
                              void* d_out, int out_size) {
    const float* feat    = (const float*)d_in[0];
    const int*   adj     = (const int*)  d_in[1];
    const float* W       = (const float*)d_in[2];
    const float* att_src = (const float*)d_in[3];
    const float* att_dst = (const float*)d_in[4];
    const float* bias    = (const float*)d_in[5];
    float* out = (float*)d_out;

    decomp_feat<<<(Bb * Nn * Dd) / 4 / 256, 256>>>(feat);
    decomp_wt<<<dim3(Dd / 32, HC / 32), 256>>>(W);
    pack_adj<<<dim3(64, 8, 4), 256>>>(adj);
    proj_mma<<<dim3(64, 8), 128>>>();
    transp_attn<<<dim3(64, 8, 4), 256>>>(att_src, att_dst);
    gat_agg<<<dim3(Hh, Nn / 128, Bb), 128>>>(bias, out);
}